// round 15
// baseline (speedup 1.0000x reference)
#include <cuda_runtime.h>
#include <cuda_fp16.h>
#include <cstdint>

// ---------------------------------------------------------------------------
// Problem constants
// ---------------------------------------------------------------------------
#define BWIN   1024
#define NTOK   49
#define CH     512
#define NH     16
#define HD     32
#define MTOT   (BWIN * NTOK)     // 50176
#define KDIM   512
#define BKE    64                // K elems per stage
#define KITERS (KDIM / BKE)      // 8
#define AST    72                // smem row stride (fp16 elems) = 144 bytes
#define MAT_BYTES   (128 * AST * 2)      // 18432
#define STAGE_BYTES (2 * MAT_BYTES)      // 36864 (A,B)
#define SMEM_BYTES  (2 * STAGE_BYTES)    // 73728 (double buffer)
#define SCALE  0.17677669529663687f

// ---------------------------------------------------------------------------
// Scratch
// ---------------------------------------------------------------------------
__device__ __half g_kv [(size_t)MTOT * 1024];   // kv projection, fp16
__device__ __half g_Ah [(size_t)MTOT * KDIM];   // inputs fp16
__device__ __half g_xh [(size_t)MTOT * KDIM];   // attention out fp16
__device__ __half g_W1h[1024 * 512];
__device__ __half g_W2h[ 512 * 512];

// ---------------------------------------------------------------------------
// Helpers
// ---------------------------------------------------------------------------
__device__ __forceinline__ uint32_t s2u(const void* p) {
    uint32_t a;
    asm("{ .reg .u64 t; cvta.to.shared.u64 t, %1; cvt.u32.u64 %0, t; }" : "=r"(a) : "l"(p));
    return a;
}

#define LDSM4(R, addr)                                                         \
    asm volatile("ldmatrix.sync.aligned.m8n8.x4.shared.b16 {%0,%1,%2,%3}, [%4];" \
                 : "=r"((R)[0]), "=r"((R)[1]), "=r"((R)[2]), "=r"((R)[3])       \
                 : "r"(addr))

#define LDSM4T(R, addr)                                                        \
    asm volatile("ldmatrix.sync.aligned.m8n8.x4.trans.shared.b16 {%0,%1,%2,%3}, [%4];" \
                 : "=r"((R)[0]), "=r"((R)[1]), "=r"((R)[2]), "=r"((R)[3])       \
                 : "r"(addr))

#define MMA16816(Cf, Af, b0, b1)                                               \
    asm volatile("mma.sync.aligned.m16n8k16.row.col.f32.f16.f16.f32 "          \
                 "{%0,%1,%2,%3}, {%4,%5,%6,%7}, {%8,%9}, {%0,%1,%2,%3};"       \
                 : "+f"((Cf)[0]), "+f"((Cf)[1]), "+f"((Cf)[2]), "+f"((Cf)[3])  \
                 : "r"((Af)[0]), "r"((Af)[1]), "r"((Af)[2]), "r"((Af)[3]),     \
                   "r"(b0), "r"(b1))

__device__ __forceinline__ uint32_t packh2(float a, float b) {
    __half2 h = __floats2half2_rn(a, b);
    return *reinterpret_cast<uint32_t*>(&h);
}

// ---------------------------------------------------------------------------
// Conversion kernels
// ---------------------------------------------------------------------------
__global__ void cvt_kernel(const float4* __restrict__ X, uint2* __restrict__ H, int n4) {
    int i = blockIdx.x * blockDim.x + threadIdx.x;
    if (i >= n4) return;
    float4 v = X[i];
    uint2 hv;
    hv.x = packh2(v.x, v.y); hv.y = packh2(v.z, v.w);
    H[i] = hv;
}

__global__ void transpose_h(const float* __restrict__ W,
                            __half* __restrict__ Th, int K, int N) {
    __shared__ float t[32][33];
    int n0 = blockIdx.x * 32, k0 = blockIdx.y * 32;
    for (int i = threadIdx.y; i < 32; i += 8)
        t[i][threadIdx.x] = W[(size_t)(k0 + i) * N + n0 + threadIdx.x];
    __syncthreads();
    for (int i = threadIdx.y; i < 32; i += 8)
        Th[(size_t)(n0 + i) * K + k0 + threadIdx.x] = __float2half_rn(t[threadIdx.x][i]);
}

// ---------------------------------------------------------------------------
// fp16 single-pass GEMM: C = A[M,K] @ B[N,K]^T + bias
// 128x128 CTA tile, 8 warps of 64x32, BK=64 stages, double-buffered cp.async
// ---------------------------------------------------------------------------
__device__ __forceinline__ void fill_stage(uint32_t sbase,
                                           const __half* const srcs[2],
                                           int k0, int tid) {
    #pragma unroll
    for (int t = 0; t < 8; t++) {
        int c   = tid + t * 256;          // 0..2047
        int mat = c >> 10;                // 0..1
        int r   = (c >> 3) & 127;         // row 0..127
        int ch  = c & 7;                  // 16B chunk in 128B row
        uint32_t dst = sbase + mat * MAT_BYTES + r * (AST * 2) + ch * 16;
        const char* src = (const char*)(srcs[mat] + (size_t)r * KDIM + k0) + ch * 16;
        asm volatile("cp.async.cg.shared.global [%0], [%1], 16;" :: "r"(dst), "l"(src));
    }
    asm volatile("cp.async.commit_group;" ::: "memory");
}

template<bool OUTH>
__global__ void __launch_bounds__(256, 2) gemm_tc(
    const __half* __restrict__ A, const __half* __restrict__ B,
    const float* __restrict__ bias, void* __restrict__ Cv, int N)
{
    extern __shared__ char smem[];
    const uint32_t sb = s2u(smem);
    const int tid = threadIdx.x, wid = tid >> 5, lane = tid & 31;
    const int wm = (wid & 1) * 64;
    const int wn = (wid >> 1) * 32;
    const int bM = blockIdx.y * 128, bN = blockIdx.x * 128;

    const __half* srcs[2] = { A + (size_t)bM * KDIM, B + (size_t)bN * KDIM };

    float acc[4][4][4];
    #pragma unroll
    for (int i = 0; i < 4; i++)
        #pragma unroll
        for (int j = 0; j < 4; j++)
            #pragma unroll
            for (int e = 0; e < 4; e++) acc[i][j][e] = 0.f;

    const int lrow  = lane & 15;
    const int lcolB = ((lane >> 4) << 3) * 2;

    fill_stage(sb, srcs, 0, tid);

    for (int it = 0; it < KITERS; it++) {
        asm volatile("cp.async.wait_group 0;" ::: "memory");
        __syncthreads();

        uint32_t st = sb + (it & 1) * STAGE_BYTES;
        #pragma unroll
        for (int ks = 0; ks < 4; ks++) {
            uint32_t kb = ks * 32 + lcolB;
            uint32_t ah[4][4], bh[2][4];
            #pragma unroll
            for (int i = 0; i < 4; i++) {
                uint32_t ra = st + (wm + i * 16 + lrow) * (AST * 2) + kb;
                LDSM4(ah[i], ra);
            }
            #pragma unroll
            for (int jj = 0; jj < 2; jj++) {
                uint32_t rb = st + MAT_BYTES + (wn + jj * 16 + lrow) * (AST * 2) + kb;
                LDSM4(bh[jj], rb);
            }
            if (ks == 0 && it + 1 < KITERS)
                fill_stage(sb + ((it + 1) & 1) * STAGE_BYTES, srcs, (it + 1) * BKE, tid);

            #pragma unroll
            for (int i = 0; i < 4; i++)
                #pragma unroll
                for (int j = 0; j < 4; j++) {
                    int jj = j >> 1, sel = j & 1;
                    MMA16816(acc[i][j], ah[i], bh[jj][sel], bh[jj][sel + 2]);
                }
        }
    }

    #pragma unroll
    for (int j = 0; j < 4; j++) {
        int c0 = bN + wn + j * 8 + (lane & 3) * 2;
        float b0 = bias[c0], b1 = bias[c0 + 1];
        #pragma unroll
        for (int i = 0; i < 4; i++) {
            int r0 = bM + wm + i * 16 + (lane >> 2);
            if (OUTH) {
                __half* C = (__half*)Cv;
                __half2 v0 = __floats2half2_rn(acc[i][j][0] + b0, acc[i][j][1] + b1);
                __half2 v1 = __floats2half2_rn(acc[i][j][2] + b0, acc[i][j][3] + b1);
                *(__half2*)&C[(size_t)r0 * N + c0]       = v0;
                *(__half2*)&C[(size_t)(r0 + 8) * N + c0] = v1;
            } else {
                float* C = (float*)Cv;
                float2 v0 = { acc[i][j][0] + b0, acc[i][j][1] + b1 };
                float2 v1 = { acc[i][j][2] + b0, acc[i][j][3] + b1 };
                *(float2*)&C[(size_t)r0 * N + c0]       = v0;
                *(float2*)&C[(size_t)(r0 + 8) * N + c0] = v1;
            }
        }
    }
}

// ---------------------------------------------------------------------------
// Tensor-core attention: block = (window, head); 64x64 padded tiles
// ---------------------------------------------------------------------------
__global__ void __launch_bounds__(128) attn_tc(
    const float* __restrict__ q_global,
    const float* __restrict__ bias_table)
{
    const int bh = blockIdx.x;
    const int b_ = bh >> 4, h = bh & 15, b = b_ >> 4;
    const int tid = threadIdx.x, wid = tid >> 5, lane = tid & 31;

    __shared__ __align__(16) __half Qh[64 * 40];
    __shared__ __align__(16) __half Kh[64 * 40];
    __shared__ __align__(16) __half Vh[64 * 40];
    __shared__ float bias_s[172];

    for (int t = tid; t < 300; t += 128) {
        ((uint32_t*)(Qh + 49 * 40))[t] = 0;
        ((uint32_t*)(Vh + 49 * 40))[t] = 0;
    }

    {
        const uint4* kv = (const uint4*)(g_kv + (size_t)(b_ * NTOK) * 1024 + h * HD);
        for (int t = tid; t < NTOK * 4; t += 128) {
            int n = t >> 2, c = t & 3;
            ((uint4*)(Kh + n * 40))[c] = kv[(size_t)n * 128 + c];
            ((uint4*)(Vh + n * 40))[c] = kv[(size_t)n * 128 + 64 + c];
        }
    }
    {
        const float4* qg = (const float4*)(q_global + (size_t)(b * NTOK) * CH + h * HD);
        for (int t = tid; t < NTOK * 8; t += 128) {
            int n = t >> 3, c = t & 7;
            float4 v = qg[(size_t)n * 128 + c];
            __half2* dst = (__half2*)(Qh + n * 40);
            dst[c * 2]     = __floats2half2_rn(v.x * SCALE, v.y * SCALE);
            dst[c * 2 + 1] = __floats2half2_rn(v.z * SCALE, v.w * SCALE);
        }
        for (int t = tid; t < 169; t += 128) bias_s[t] = bias_table[t * NH + h];
    }
    __syncthreads();

    const uint32_t qbu = s2u(Qh), kbu = s2u(Kh), vbu = s2u(Vh);
    const int lr = lane & 15;
    const int lc = (lane >> 4) * 8;

    float sacc[8][4];
    #pragma unroll
    for (int jt = 0; jt < 8; jt++)
        #pragma unroll
        for (int e = 0; e < 4; e++) sacc[jt][e] = 0.f;

    #pragma unroll
    for (int kt = 0; kt < 2; kt++) {
        uint32_t qa[4];
        LDSM4(qa, qbu + ((16 * wid + lr) * 40 + kt * 16 + lc) * 2);
        #pragma unroll
        for (int jt = 0; jt < 4; jt++) {
            uint32_t kf[4];
            LDSM4(kf, kbu + ((16 * jt + lr) * 40 + kt * 16 + lc) * 2);
            MMA16816(sacc[jt * 2 + 0], qa, kf[0], kf[2]);
            MMA16816(sacc[jt * 2 + 1], qa, kf[1], kf[3]);
        }
    }

    const int r0 = 16 * wid + (lane >> 2);
    const int r1 = r0 + 8;
    const int ih0 = r0 / 7, iw0 = r0 - ih0 * 7;
    const int ih1 = r1 / 7, iw1 = r1 - ih1 * 7;
    #pragma unroll
    for (int jt = 0; jt < 8; jt++) {
        #pragma unroll
        for (int e = 0; e < 2; e++) {
            int j = jt * 8 + (lane & 3) * 2 + e;
            if (j < NTOK) {
                int jh = j / 7, jw = j - jh * 7;
                int i0 = (ih0 - jh + 6) * 13 + (iw0 - jw + 6);
                int i1 = (ih1 - jh + 6) * 13 + (iw1 - jw + 6);
                i0 = min(168, max(0, i0));
                i1 = min(168, max(0, i1));
                sacc[jt][e]     += bias_s[i0];
                sacc[jt][2 + e] += bias_s[i1];
            } else {
                sacc[jt][e]     = -1e30f;
                sacc[jt][2 + e] = -1e30f;
            }
        }
    }

    float m0 = -1e30f, m1 = -1e30f;
    #pragma unroll
    for (int jt = 0; jt < 8; jt++) {
        m0 = fmaxf(m0, fmaxf(sacc[jt][0], sacc[jt][1]));
        m1 = fmaxf(m1, fmaxf(sacc[jt][2], sacc[jt][3]));
    }
    m0 = fmaxf(m0, __shfl_xor_sync(0xffffffffu, m0, 1));
    m0 = fmaxf(m0, __shfl_xor_sync(0xffffffffu, m0, 2));
    m1 = fmaxf(m1, __shfl_xor_sync(0xffffffffu, m1, 1));
    m1 = fmaxf(m1, __shfl_xor_sync(0xffffffffu, m1, 2));
    float s0 = 0.f, s1 = 0.f;
    #pragma unroll
    for (int jt = 0; jt < 8; jt++) {
        sacc[jt][0] = __expf(sacc[jt][0] - m0); s0 += sacc[jt][0];
        sacc[jt][1] = __expf(sacc[jt][1] - m0); s0 += sacc[jt][1];
        sacc[jt][2] = __expf(sacc[jt][2] - m1); s1 += sacc[jt][2];
        sacc[jt][3] = __expf(sacc[jt][3] - m1); s1 += sacc[jt][3];
    }
    s0 += __shfl_xor_sync(0xffffffffu, s0, 1);
    s0 += __shfl_xor_sync(0xffffffffu, s0, 2);
    s1 += __shfl_xor_sync(0xffffffffu, s1, 1);
    s1 += __shfl_xor_sync(0xffffffffu, s1, 2);
    const float inv0 = 1.0f / s0, inv1 = 1.0f / s1;

    uint32_t pa[4][4];
    #pragma unroll
    for (int kt = 0; kt < 4; kt++) {
        pa[kt][0] = packh2(sacc[2 * kt][0] * inv0,     sacc[2 * kt][1] * inv0);
        pa[kt][1] = packh2(sacc[2 * kt][2] * inv1,     sacc[2 * kt][3] * inv1);
        pa[kt][2] = packh2(sacc[2 * kt + 1][0] * inv0, sacc[2 * kt + 1][1] * inv0);
        pa[kt][3] = packh2(sacc[2 * kt + 1][2] * inv1, sacc[2 * kt + 1][3] * inv1);
    }

    float xacc[4][4];
    #pragma unroll
    for (int nt = 0; nt < 4; nt++)
        #pragma unroll
        for (int e = 0; e < 4; e++) xacc[nt][e] = 0.f;

    #pragma unroll
    for (int kt = 0; kt < 4; kt++) {
        uint32_t bv0[4], bv1[4];
        LDSM4T(bv0, vbu + ((16 * kt + lr) * 40 + lc) * 2);
        LDSM4T(bv1, vbu + ((16 * kt + lr) * 40 + 16 + lc) * 2);
        MMA16816(xacc[0], pa[kt], bv0[0], bv0[1]);
        MMA16816(xacc[1], pa[kt], bv0[2], bv0[3]);
        MMA16816(xacc[2], pa[kt], bv1[0], bv1[1]);
        MMA16816(xacc[3], pa[kt], bv1[2], bv1[3]);
    }

    if (r0 < NTOK) {
        size_t base = (size_t)(b_ * NTOK + r0) * CH + h * HD + (lane & 3) * 2;
        #pragma unroll
        for (int nt = 0; nt < 4; nt++) {
            __half2 hv = __floats2half2_rn(xacc[nt][0], xacc[nt][1]);
            *(__half2*)(g_xh + base + nt * 8) = hv;
        }
    }
    if (r1 < NTOK) {
        size_t base = (size_t)(b_ * NTOK + r1) * CH + h * HD + (lane & 3) * 2;
        #pragma unroll
        for (int nt = 0; nt < 4; nt++) {
            __half2 hv = __floats2half2_rn(xacc[nt][2], xacc[nt][3]);
            *(__half2*)(g_xh + base + nt * 8) = hv;
        }
    }
}

// ---------------------------------------------------------------------------
// Launch
// ---------------------------------------------------------------------------
extern "C" void kernel_launch(void* const* d_in, const int* in_sizes, int n_in,
                              void* d_out, int out_size)
{
    const float* inputs     = (const float*)d_in[0];
    const float* q_global   = (const float*)d_in[1];
    const float* qkv_w      = (const float*)d_in[2];
    const float* qkv_b      = (const float*)d_in[3];
    const float* bias_table = (const float*)d_in[4];
    const float* proj_w     = (const float*)d_in[5];
    const float* proj_b     = (const float*)d_in[6];
    float*       out        = (float*)d_out;

    __half *kv_ptr, *Ah, *Xh, *W1h, *W2h;
    cudaGetSymbolAddress((void**)&kv_ptr, g_kv);
    cudaGetSymbolAddress((void**)&Ah,  g_Ah);
    cudaGetSymbolAddress((void**)&Xh,  g_xh);
    cudaGetSymbolAddress((void**)&W1h, g_W1h);
    cudaGetSymbolAddress((void**)&W2h, g_W2h);

    cudaFuncSetAttribute(gemm_tc<true>,  cudaFuncAttributeMaxDynamicSharedMemorySize, SMEM_BYTES);
    cudaFuncSetAttribute(gemm_tc<false>, cudaFuncAttributeMaxDynamicSharedMemorySize, SMEM_BYTES);

    {
        int n4 = MTOT * KDIM / 4;
        cvt_kernel<<<(n4 + 255) / 256, 256>>>((const float4*)inputs, (uint2*)Ah, n4);
        transpose_h<<<dim3(1024 / 32, 512 / 32), dim3(32, 8)>>>(qkv_w, W1h, 512, 1024);
        transpose_h<<<dim3(512 / 32, 512 / 32), dim3(32, 8)>>>(proj_w, W2h, 512, 512);
    }

    // 1) kv = inputs @ qkv_w + qkv_b  -> fp16
    gemm_tc<true><<<dim3(1024 / 128, MTOT / 128), 256, SMEM_BYTES>>>(
        Ah, W1h, qkv_b, kv_ptr, 1024);

    // 2) attention (tensor-core)
    attn_tc<<<BWIN * NH, 128>>>(q_global, bias_table);

    // 3) out = x @ proj_w + proj_b -> fp32
    gemm_tc<false><<<dim3(512 / 128, MTOT / 128), 256, SMEM_BYTES>>>(
        Xh, W2h, proj_b, out, 512);
}

// round 17
// speedup vs baseline: 1.5138x; 1.5138x over previous
#include <cuda_runtime.h>
#include <cuda_fp16.h>
#include <cstdint>

// ---------------------------------------------------------------------------
// Problem constants
// ---------------------------------------------------------------------------
#define BWIN   1024
#define NTOK   49
#define CH     512
#define NH     16
#define HD     32
#define MTOT   (BWIN * NTOK)     // 50176
#define KDIM   512
#define BKE    32
#define KITERS (KDIM / BKE)      // 16
#define AST    40                // smem row stride (fp16 elems)
#define MAT_BYTES   (128 * AST * 2)      // 10240
#define STAGE_BYTES (2 * MAT_BYTES)      // 20480 (A,B)
#define SMEM_BYTES  (3 * STAGE_BYTES)    // 61440 (triple buffer)
#define SCALE  0.17677669529663687f

// ---------------------------------------------------------------------------
// Scratch
// ---------------------------------------------------------------------------
__device__ __half g_kv [(size_t)MTOT * 1024];   // kv projection, fp16
__device__ __half g_Ah [(size_t)MTOT * KDIM];   // inputs fp16
__device__ __half g_xh [(size_t)MTOT * KDIM];   // attention out fp16
__device__ __half g_W1h[1024 * 512];
__device__ __half g_W2h[ 512 * 512];

// ---------------------------------------------------------------------------
// Helpers
// ---------------------------------------------------------------------------
__device__ __forceinline__ uint32_t s2u(const void* p) {
    uint32_t a;
    asm("{ .reg .u64 t; cvta.to.shared.u64 t, %1; cvt.u32.u64 %0, t; }" : "=r"(a) : "l"(p));
    return a;
}

#define LDSM4(R, addr)                                                         \
    asm volatile("ldmatrix.sync.aligned.m8n8.x4.shared.b16 {%0,%1,%2,%3}, [%4];" \
                 : "=r"((R)[0]), "=r"((R)[1]), "=r"((R)[2]), "=r"((R)[3])       \
                 : "r"(addr))

#define LDSM4T(R, addr)                                                        \
    asm volatile("ldmatrix.sync.aligned.m8n8.x4.trans.shared.b16 {%0,%1,%2,%3}, [%4];" \
                 : "=r"((R)[0]), "=r"((R)[1]), "=r"((R)[2]), "=r"((R)[3])       \
                 : "r"(addr))

#define MMA16816(Cf, Af, b0, b1)                                               \
    asm volatile("mma.sync.aligned.m16n8k16.row.col.f32.f16.f16.f32 "          \
                 "{%0,%1,%2,%3}, {%4,%5,%6,%7}, {%8,%9}, {%0,%1,%2,%3};"       \
                 : "+f"((Cf)[0]), "+f"((Cf)[1]), "+f"((Cf)[2]), "+f"((Cf)[3])  \
                 : "r"((Af)[0]), "r"((Af)[1]), "r"((Af)[2]), "r"((Af)[3]),     \
                   "r"(b0), "r"(b1))

__device__ __forceinline__ uint32_t packh2(float a, float b) {
    __half2 h = __floats2half2_rn(a, b);
    return *reinterpret_cast<uint32_t*>(&h);
}

// ---------------------------------------------------------------------------
// Conversion kernels
// ---------------------------------------------------------------------------
__global__ void cvt_kernel(const float4* __restrict__ X, uint2* __restrict__ H, int n4) {
    int i = blockIdx.x * blockDim.x + threadIdx.x;
    if (i >= n4) return;
    float4 v = X[i];
    uint2 hv;
    hv.x = packh2(v.x, v.y); hv.y = packh2(v.z, v.w);
    H[i] = hv;
}

__global__ void transpose_h(const float* __restrict__ W,
                            __half* __restrict__ Th, int K, int N) {
    __shared__ float t[32][33];
    int n0 = blockIdx.x * 32, k0 = blockIdx.y * 32;
    for (int i = threadIdx.y; i < 32; i += 8)
        t[i][threadIdx.x] = W[(size_t)(k0 + i) * N + n0 + threadIdx.x];
    __syncthreads();
    for (int i = threadIdx.y; i < 32; i += 8)
        Th[(size_t)(n0 + i) * K + k0 + threadIdx.x] = __float2half_rn(t[threadIdx.x][i]);
}

// ---------------------------------------------------------------------------
// fp16 single-pass GEMM: C = A[M,K] @ B[N,K]^T + bias
// 128x128 CTA tile, 8 warps of 64x32, triple-buffered cp.async (distance 2)
// ---------------------------------------------------------------------------
__device__ __forceinline__ void fill_stage(uint32_t sbase,
                                           const __half* const srcs[2],
                                           int k0, int tid) {
    #pragma unroll
    for (int t = 0; t < 4; t++) {
        int c   = tid + t * 256;          // 0..1023
        int mat = c >> 9;                 // 0..1
        int r   = (c >> 2) & 127;
        int ch  = c & 3;
        uint32_t dst = sbase + mat * MAT_BYTES + r * (AST * 2) + ch * 16;
        const char* src = (const char*)(srcs[mat] + (size_t)r * KDIM + k0) + ch * 16;
        asm volatile("cp.async.cg.shared.global [%0], [%1], 16;" :: "r"(dst), "l"(src));
    }
    asm volatile("cp.async.commit_group;" ::: "memory");
}

template<bool OUTH>
__global__ void __launch_bounds__(256, 2) gemm_tc(
    const __half* __restrict__ A, const __half* __restrict__ B,
    const float* __restrict__ bias, void* __restrict__ Cv, int N)
{
    extern __shared__ char smem[];
    const uint32_t sb = s2u(smem);
    const int tid = threadIdx.x, wid = tid >> 5, lane = tid & 31;
    const int wm = (wid & 1) * 64;
    const int wn = (wid >> 1) * 32;
    const int bM = blockIdx.y * 128, bN = blockIdx.x * 128;

    const __half* srcs[2] = { A + (size_t)bM * KDIM, B + (size_t)bN * KDIM };

    float acc[4][4][4];
    #pragma unroll
    for (int i = 0; i < 4; i++)
        #pragma unroll
        for (int j = 0; j < 4; j++)
            #pragma unroll
            for (int e = 0; e < 4; e++) acc[i][j][e] = 0.f;

    const int lrow  = lane & 15;
    const int lcolB = ((lane >> 4) << 3) * 2;

    fill_stage(sb, srcs, 0, tid);
    fill_stage(sb + STAGE_BYTES, srcs, BKE, tid);

    for (int it = 0; it < KITERS; it++) {
        if (it + 1 < KITERS)
            asm volatile("cp.async.wait_group 1;" ::: "memory");
        else
            asm volatile("cp.async.wait_group 0;" ::: "memory");
        __syncthreads();

        uint32_t st = sb + (it % 3) * STAGE_BYTES;
        #pragma unroll
        for (int ks = 0; ks < 2; ks++) {
            uint32_t kb = ks * 32 + lcolB;
            uint32_t ah[4][4], bh[2][4];
            #pragma unroll
            for (int i = 0; i < 4; i++) {
                uint32_t ra = st + (wm + i * 16 + lrow) * (AST * 2) + kb;
                LDSM4(ah[i], ra);
            }
            #pragma unroll
            for (int jj = 0; jj < 2; jj++) {
                uint32_t rb = st + MAT_BYTES + (wn + jj * 16 + lrow) * (AST * 2) + kb;
                LDSM4(bh[jj], rb);
            }
            if (ks == 0 && it + 2 < KITERS)
                fill_stage(sb + ((it + 2) % 3) * STAGE_BYTES, srcs, (it + 2) * BKE, tid);

            #pragma unroll
            for (int i = 0; i < 4; i++)
                #pragma unroll
                for (int j = 0; j < 4; j++) {
                    int jj = j >> 1, sel = j & 1;
                    MMA16816(acc[i][j], ah[i], bh[jj][sel], bh[jj][sel + 2]);
                }
        }
    }

    #pragma unroll
    for (int j = 0; j < 4; j++) {
        int c0 = bN + wn + j * 8 + (lane & 3) * 2;
        float b0 = bias[c0], b1 = bias[c0 + 1];
        #pragma unroll
        for (int i = 0; i < 4; i++) {
            int r0 = bM + wm + i * 16 + (lane >> 2);
            if (OUTH) {
                __half* C = (__half*)Cv;
                __half2 v0 = __floats2half2_rn(acc[i][j][0] + b0, acc[i][j][1] + b1);
                __half2 v1 = __floats2half2_rn(acc[i][j][2] + b0, acc[i][j][3] + b1);
                *(__half2*)&C[(size_t)r0 * N + c0]       = v0;
                *(__half2*)&C[(size_t)(r0 + 8) * N + c0] = v1;
            } else {
                float* C = (float*)Cv;
                float2 v0 = { acc[i][j][0] + b0, acc[i][j][1] + b1 };
                float2 v1 = { acc[i][j][2] + b0, acc[i][j][3] + b1 };
                *(float2*)&C[(size_t)r0 * N + c0]       = v0;
                *(float2*)&C[(size_t)(r0 + 8) * N + c0] = v1;
            }
        }
    }
}

// ---------------------------------------------------------------------------
// Tensor-core attention: block = (window, head); 64x64 padded tiles
// ---------------------------------------------------------------------------
__global__ void __launch_bounds__(128) attn_tc(
    const float* __restrict__ q_global,
    const float* __restrict__ bias_table)
{
    const int bh = blockIdx.x;
    const int b_ = bh >> 4, h = bh & 15, b = b_ >> 4;
    const int tid = threadIdx.x, wid = tid >> 5, lane = tid & 31;

    __shared__ __align__(16) __half Qh[64 * 40];
    __shared__ __align__(16) __half Kh[64 * 40];
    __shared__ __align__(16) __half Vh[64 * 40];
    __shared__ float bias_s[172];

    for (int t = tid; t < 300; t += 128) {
        ((uint32_t*)(Qh + 49 * 40))[t] = 0;
        ((uint32_t*)(Vh + 49 * 40))[t] = 0;
    }

    {
        const uint4* kv = (const uint4*)(g_kv + (size_t)(b_ * NTOK) * 1024 + h * HD);
        for (int t = tid; t < NTOK * 4; t += 128) {
            int n = t >> 2, c = t & 3;
            ((uint4*)(Kh + n * 40))[c] = kv[(size_t)n * 128 + c];
            ((uint4*)(Vh + n * 40))[c] = kv[(size_t)n * 128 + 64 + c];
        }
    }
    {
        const float4* qg = (const float4*)(q_global + (size_t)(b * NTOK) * CH + h * HD);
        for (int t = tid; t < NTOK * 8; t += 128) {
            int n = t >> 3, c = t & 7;
            float4 v = qg[(size_t)n * 128 + c];
            __half2* dst = (__half2*)(Qh + n * 40);
            dst[c * 2]     = __floats2half2_rn(v.x * SCALE, v.y * SCALE);
            dst[c * 2 + 1] = __floats2half2_rn(v.z * SCALE, v.w * SCALE);
        }
        for (int t = tid; t < 169; t += 128) bias_s[t] = bias_table[t * NH + h];
    }
    __syncthreads();

    const uint32_t qbu = s2u(Qh), kbu = s2u(Kh), vbu = s2u(Vh);
    const int lr = lane & 15;
    const int lc = (lane >> 4) * 8;

    float sacc[8][4];
    #pragma unroll
    for (int jt = 0; jt < 8; jt++)
        #pragma unroll
        for (int e = 0; e < 4; e++) sacc[jt][e] = 0.f;

    #pragma unroll
    for (int kt = 0; kt < 2; kt++) {
        uint32_t qa[4];
        LDSM4(qa, qbu + ((16 * wid + lr) * 40 + kt * 16 + lc) * 2);
        #pragma unroll
        for (int jt = 0; jt < 4; jt++) {
            uint32_t kf[4];
            LDSM4(kf, kbu + ((16 * jt + lr) * 40 + kt * 16 + lc) * 2);
            MMA16816(sacc[jt * 2 + 0], qa, kf[0], kf[2]);
            MMA16816(sacc[jt * 2 + 1], qa, kf[1], kf[3]);
        }
    }

    const int r0 = 16 * wid + (lane >> 2);
    const int r1 = r0 + 8;
    const int ih0 = r0 / 7, iw0 = r0 - ih0 * 7;
    const int ih1 = r1 / 7, iw1 = r1 - ih1 * 7;
    #pragma unroll
    for (int jt = 0; jt < 8; jt++) {
        #pragma unroll
        for (int e = 0; e < 2; e++) {
            int j = jt * 8 + (lane & 3) * 2 + e;
            if (j < NTOK) {
                int jh = j / 7, jw = j - jh * 7;
                int i0 = (ih0 - jh + 6) * 13 + (iw0 - jw + 6);
                int i1 = (ih1 - jh + 6) * 13 + (iw1 - jw + 6);
                i0 = min(168, max(0, i0));
                i1 = min(168, max(0, i1));
                sacc[jt][e]     += bias_s[i0];
                sacc[jt][2 + e] += bias_s[i1];
            } else {
                sacc[jt][e]     = -1e30f;
                sacc[jt][2 + e] = -1e30f;
            }
        }
    }

    float m0 = -1e30f, m1 = -1e30f;
    #pragma unroll
    for (int jt = 0; jt < 8; jt++) {
        m0 = fmaxf(m0, fmaxf(sacc[jt][0], sacc[jt][1]));
        m1 = fmaxf(m1, fmaxf(sacc[jt][2], sacc[jt][3]));
    }
    m0 = fmaxf(m0, __shfl_xor_sync(0xffffffffu, m0, 1));
    m0 = fmaxf(m0, __shfl_xor_sync(0xffffffffu, m0, 2));
    m1 = fmaxf(m1, __shfl_xor_sync(0xffffffffu, m1, 1));
    m1 = fmaxf(m1, __shfl_xor_sync(0xffffffffu, m1, 2));
    float s0 = 0.f, s1 = 0.f;
    #pragma unroll
    for (int jt = 0; jt < 8; jt++) {
        sacc[jt][0] = __expf(sacc[jt][0] - m0); s0 += sacc[jt][0];
        sacc[jt][1] = __expf(sacc[jt][1] - m0); s0 += sacc[jt][1];
        sacc[jt][2] = __expf(sacc[jt][2] - m1); s1 += sacc[jt][2];
        sacc[jt][3] = __expf(sacc[jt][3] - m1); s1 += sacc[jt][3];
    }
    s0 += __shfl_xor_sync(0xffffffffu, s0, 1);
    s0 += __shfl_xor_sync(0xffffffffu, s0, 2);
    s1 += __shfl_xor_sync(0xffffffffu, s1, 1);
    s1 += __shfl_xor_sync(0xffffffffu, s1, 2);
    const float inv0 = 1.0f / s0, inv1 = 1.0f / s1;

    uint32_t pa[4][4];
    #pragma unroll
    for (int kt = 0; kt < 4; kt++) {
        pa[kt][0] = packh2(sacc[2 * kt][0] * inv0,     sacc[2 * kt][1] * inv0);
        pa[kt][1] = packh2(sacc[2 * kt][2] * inv1,     sacc[2 * kt][3] * inv1);
        pa[kt][2] = packh2(sacc[2 * kt + 1][0] * inv0, sacc[2 * kt + 1][1] * inv0);
        pa[kt][3] = packh2(sacc[2 * kt + 1][2] * inv1, sacc[2 * kt + 1][3] * inv1);
    }

    float xacc[4][4];
    #pragma unroll
    for (int nt = 0; nt < 4; nt++)
        #pragma unroll
        for (int e = 0; e < 4; e++) xacc[nt][e] = 0.f;

    #pragma unroll
    for (int kt = 0; kt < 4; kt++) {
        uint32_t bv0[4], bv1[4];
        LDSM4T(bv0, vbu + ((16 * kt + lr) * 40 + lc) * 2);
        LDSM4T(bv1, vbu + ((16 * kt + lr) * 40 + 16 + lc) * 2);
        MMA16816(xacc[0], pa[kt], bv0[0], bv0[1]);
        MMA16816(xacc[1], pa[kt], bv0[2], bv0[3]);
        MMA16816(xacc[2], pa[kt], bv1[0], bv1[1]);
        MMA16816(xacc[3], pa[kt], bv1[2], bv1[3]);
    }

    if (r0 < NTOK) {
        size_t base = (size_t)(b_ * NTOK + r0) * CH + h * HD + (lane & 3) * 2;
        #pragma unroll
        for (int nt = 0; nt < 4; nt++) {
            __half2 hv = __floats2half2_rn(xacc[nt][0], xacc[nt][1]);
            *(__half2*)(g_xh + base + nt * 8) = hv;
        }
    }
    if (r1 < NTOK) {
        size_t base = (size_t)(b_ * NTOK + r1) * CH + h * HD + (lane & 3) * 2;
        #pragma unroll
        for (int nt = 0; nt < 4; nt++) {
            __half2 hv = __floats2half2_rn(xacc[nt][2], xacc[nt][3]);
            *(__half2*)(g_xh + base + nt * 8) = hv;
        }
    }
}

// ---------------------------------------------------------------------------
// Launch
// ---------------------------------------------------------------------------
extern "C" void kernel_launch(void* const* d_in, const int* in_sizes, int n_in,
                              void* d_out, int out_size)
{
    const float* inputs     = (const float*)d_in[0];
    const float* q_global   = (const float*)d_in[1];
    const float* qkv_w      = (const float*)d_in[2];
    const float* qkv_b      = (const float*)d_in[3];
    const float* bias_table = (const float*)d_in[4];
    const float* proj_w     = (const float*)d_in[5];
    const float* proj_b     = (const float*)d_in[6];
    float*       out        = (float*)d_out;

    __half *kv_ptr, *Ah, *Xh, *W1h, *W2h;
    cudaGetSymbolAddress((void**)&kv_ptr, g_kv);
    cudaGetSymbolAddress((void**)&Ah,  g_Ah);
    cudaGetSymbolAddress((void**)&Xh,  g_xh);
    cudaGetSymbolAddress((void**)&W1h, g_W1h);
    cudaGetSymbolAddress((void**)&W2h, g_W2h);

    cudaFuncSetAttribute(gemm_tc<true>,  cudaFuncAttributeMaxDynamicSharedMemorySize, SMEM_BYTES);
    cudaFuncSetAttribute(gemm_tc<false>, cudaFuncAttributeMaxDynamicSharedMemorySize, SMEM_BYTES);

    {
        int n4 = MTOT * KDIM / 4;
        cvt_kernel<<<(n4 + 255) / 256, 256>>>((const float4*)inputs, (uint2*)Ah, n4);
        transpose_h<<<dim3(1024 / 32, 512 / 32), dim3(32, 8)>>>(qkv_w, W1h, 512, 1024);
        transpose_h<<<dim3(512 / 32, 512 / 32), dim3(32, 8)>>>(proj_w, W2h, 512, 512);
    }

    // 1) kv = inputs @ qkv_w + qkv_b  -> fp16
    gemm_tc<true><<<dim3(1024 / 128, MTOT / 128), 256, SMEM_BYTES>>>(
        Ah, W1h, qkv_b, kv_ptr, 1024);

    // 2) attention (tensor-core)
    attn_tc<<<BWIN * NH, 128>>>(q_global, bias_table);

    // 3) out = x @ proj_w + proj_b -> fp32
    gemm_tc<false><<<dim3(512 / 128, MTOT / 128), 256, SMEM_BYTES>>>(
        Xh, W2h, proj_b, out, 512);
}